// round 13
// baseline (speedup 1.0000x reference)
#include <cuda_runtime.h>
#include <cuda_fp16.h>
#include <cstdint>

#define TPB   128
#define TILES 8
#define RS    40   // A-tile row stride in halves (80B): conflict-free frag LDS

__device__ __forceinline__ uint32_t h2u(__half2 v) {
    return *(uint32_t*)&v;
}

__global__ __launch_bounds__(TPB, 4) void dlrm_kernel(
    const int*    __restrict__ user_id,
    const int*    __restrict__ item_id,
    const int*    __restrict__ cat_id,
    const float2* __restrict__ dense,
    const float4* __restrict__ user_t,   // [NUM_USERS, 8] as [., 2] float4
    const float4* __restrict__ item_t,
    const float4* __restrict__ cat_t,
    const float*  __restrict__ w1,       // [26,16] row-major
    const float*  __restrict__ b1,       // [16]
    const float*  __restrict__ w2,       // [16]
    const float*  __restrict__ b2,       // [1]
    float*        __restrict__ out,
    int batch)
{
    // Per-warp A tile: 32 samples x 32 feature cols (cols 26..31 zero), fp16.
    __shared__ __align__(16) __half sA[4][32 * RS];

    const int tid  = threadIdx.x;
    const int lane = tid & 31;
    const int wid  = tid >> 5;
    const int c    = lane & 3;    // threadID_in_group (fragment col selector)
    const int g    = lane >> 2;   // groupID (fragment row selector)
    const int p    = lane >> 1;   // gather pair index
    const int h    = lane & 1;    // which 16B half of the 32B row

    __half* A = sA[wid];

    // ---- one-time prologue (per warp) ----
    // B fragments (weights w1 as fp16), resident: bf[nt][ks][i]
    // b-frag layout m16n8k16: reg i holds k = 16ks + 2c + 8i (+1), n = 8nt + g
    uint32_t bf[2][2][2];
#pragma unroll
    for (int nt = 0; nt < 2; nt++)
#pragma unroll
        for (int ks = 0; ks < 2; ks++)
#pragma unroll
            for (int i = 0; i < 2; i++) {
                int k0 = 16 * ks + 2 * c + 8 * i;
                int n  = 8 * nt + g;
                float f0 = (k0     < 26) ? __ldg(w1 + k0 * 16 + n)       : 0.0f;
                float f1 = (k0 + 1 < 26) ? __ldg(w1 + (k0 + 1) * 16 + n) : 0.0f;
                bf[nt][ks][i] = h2u(__float22half2_rn(make_float2(f0, f1)));
            }
    // per-lane epilogue constants: this lane's 4 hidden cols are
    // {2c, 2c+1, 8+2c, 9+2c}
    float wv[4], bv[4];
#pragma unroll
    for (int q = 0; q < 4; q++) {
        int j = 2 * c + (q & 1) + 8 * (q >> 1);
        wv[q] = __ldg(w2 + j);
        bv[q] = __ldg(b1 + j);
    }
    const float b2v = __ldg(b2);

    // zero pad cols 26..31 of this lane's row (B is zero there too, but A must
    // be finite: garbage fp16 could be NaN and NaN*0 = NaN)
    *(uint32_t*)&A[lane * RS + 26] = 0u;
    *(uint32_t*)&A[lane * RS + 28] = 0u;
    *(uint32_t*)&A[lane * RS + 30] = 0u;

    const int warpBase0 = blockIdx.x * (TPB * TILES) + wid * 32;

    // ---- gather for tile t into registers (all 6 row loads + dense in flight)
    float4 rbuf[6];
    float2 dn;
    auto gather = [&](int t) {
        const int tb = warpBase0 + t * TPB;
        const int ge = tb + 2 * p;
#pragma unroll
        for (int T = 0; T < 3; T++) {
            const int* __restrict__ idp =
                (T == 0) ? user_id : (T == 1) ? item_id : cat_id;
            const float4* __restrict__ tab =
                (T == 0) ? user_t : (T == 1) ? item_t : cat_t;
            int2 id2 = __ldcs((const int2*)(idp + ge));
            rbuf[T * 2 + 0] = tab[(long)id2.x * 2 + h];   // row 2p,   half h
            rbuf[T * 2 + 1] = tab[(long)id2.y * 2 + h];   // row 2p+1, half h
        }
        dn = __ldcs(dense + tb + lane);
    };

    gather(0);

    for (int t = 0; t < TILES; t++) {
        const int tb = warpBase0 + t * TPB;

        // ---- STS: convert f32 -> f16 and stage into A tile ----
#pragma unroll
        for (int T = 0; T < 3; T++) {
#pragma unroll
            for (int b = 0; b < 2; b++) {       // b=0: row 2p, b=1: row 2p+1
                float4 v = rbuf[T * 2 + b];
                uint2 hv;
                hv.x = h2u(__float22half2_rn(make_float2(v.x, v.y)));
                hv.y = h2u(__float22half2_rn(make_float2(v.z, v.w)));
                int row = 2 * p + b;
                // cols 8T+4h .. +3  -> half index 8T+4h
                *(uint2*)&A[row * RS + 8 * T + 4 * h] = hv;
            }
        }
        // dense -> cols 24,25 of own row (row = lane)
        *(uint32_t*)&A[lane * RS + 24] =
            h2u(__float22half2_rn(make_float2(dn.x, dn.y)));
        __syncwarp();

        // ---- issue next tile's gathers now; MMA+epilogue below covers them
        if (t + 1 < TILES) gather(t + 1);

        // ---- layer 1 via mma.sync m16n8k16 (fp16 in, f32 acc) ----
        // D[32 samples, 16 hidden] = A[32,32] @ W, 2 m-tiles x 2 n-tiles x 2 k
        float d[2][2][4];
#pragma unroll
        for (int mt = 0; mt < 2; mt++)
#pragma unroll
            for (int nt = 0; nt < 2; nt++) {
                d[mt][nt][0] = d[mt][nt][1] = d[mt][nt][2] = d[mt][nt][3] = 0.f;
            }
#pragma unroll
        for (int mt = 0; mt < 2; mt++)
#pragma unroll
            for (int ks = 0; ks < 2; ks++) {
                // A fragment: a0:(16mt+g, 16ks+2c) a1:(+8 row) a2:(+8 k) a3:both
                int r0 = (16 * mt + g) * RS + 16 * ks + 2 * c;
                uint32_t a0 = *(uint32_t*)&A[r0];
                uint32_t a1 = *(uint32_t*)&A[r0 + 8 * RS];
                uint32_t a2 = *(uint32_t*)&A[r0 + 8];
                uint32_t a3 = *(uint32_t*)&A[r0 + 8 * RS + 8];
#pragma unroll
                for (int nt = 0; nt < 2; nt++) {
                    asm volatile(
                        "mma.sync.aligned.m16n8k16.row.col.f32.f16.f16.f32 "
                        "{%0,%1,%2,%3}, {%4,%5,%6,%7}, {%8,%9}, {%0,%1,%2,%3};"
                        : "+f"(d[mt][nt][0]), "+f"(d[mt][nt][1]),
                          "+f"(d[mt][nt][2]), "+f"(d[mt][nt][3])
                        : "r"(a0), "r"(a1), "r"(a2), "r"(a3),
                          "r"(bf[nt][ks][0]), "r"(bf[nt][ks][1]));
                }
            }

        // ---- epilogue: bias+relu+w2 partials, quad reduce, sigmoid, store ----
        // P[q] = partial logit of sample row (g + 8q) over this lane's 4 cols
        float P[4];
#pragma unroll
        for (int mt = 0; mt < 2; mt++)
#pragma unroll
            for (int rr = 0; rr < 2; rr++) {   // rr=0: c0,c1  rr=1: c2,c3
                float s = 0.f;
                s = fmaf(fmaxf(d[mt][0][2 * rr]     + bv[0], 0.f), wv[0], s);
                s = fmaf(fmaxf(d[mt][0][2 * rr + 1] + bv[1], 0.f), wv[1], s);
                s = fmaf(fmaxf(d[mt][1][2 * rr]     + bv[2], 0.f), wv[2], s);
                s = fmaf(fmaxf(d[mt][1][2 * rr + 1] + bv[3], 0.f), wv[3], s);
                P[2 * mt + rr] = s;
            }
#pragma unroll
        for (int q = 0; q < 4; q++) {
            P[q] += __shfl_xor_sync(0xFFFFFFFFu, P[q], 1);
            P[q] += __shfl_xor_sync(0xFFFFFFFFu, P[q], 2);
        }
        // lane writes sample row g + 8c
        float l = ((c == 0) ? P[0] : (c == 1) ? P[1] : (c == 2) ? P[2] : P[3])
                  + b2v;
        float e = __expf(-l);
        __stcs(out + tb + g + 8 * c, __fdividef(1.0f, 1.0f + e));

        __syncwarp();   // all frag LDS done before next iteration's STS
    }
}

extern "C" void kernel_launch(void* const* d_in, const int* in_sizes, int n_in,
                              void* d_out, int out_size) {
    const int*    user_id = (const int*)d_in[0];
    const int*    item_id = (const int*)d_in[1];
    const int*    cat_id  = (const int*)d_in[2];
    const float2* dense   = (const float2*)d_in[3];
    const float4* user_t  = (const float4*)d_in[4];
    const float4* item_t  = (const float4*)d_in[5];
    const float4* cat_t   = (const float4*)d_in[6];
    const float*  w1      = (const float*)d_in[7];
    const float*  b1      = (const float*)d_in[8];
    const float*  w2      = (const float*)d_in[9];
    const float*  b2      = (const float*)d_in[10];
    float*        out     = (float*)d_out;

    const int batch  = in_sizes[0];
    const int blocks = batch / (TPB * TILES);   // 4194304 / 1024 = 4096

    dlrm_kernel<<<blocks, TPB>>>(user_id, item_id, cat_id, dense,
                                 user_t, item_t, cat_t,
                                 w1, b1, w2, b2, out, batch);
}